// round 12
// baseline (speedup 1.0000x reference)
#include <cuda_runtime.h>
#include <cuda_bf16.h>
#include <cuda_fp16.h>
#include <math.h>

#define B_   4
#define S_   1024
#define D_   512
#define H_   8
#define DK_  64
#define F_   2048
#define V_   32000
#define M_   4096

typedef unsigned short u16;
typedef unsigned int   u32;
typedef unsigned long long u64;

// ---------------- scratch (device globals: allocation-free) ----------------
__device__ float g_x [M_*D_];                    // residual stream fp32
__device__ u16   g_hf[M_*D_];                    // in-layer LN out, fp16
__device__ u16   g_hh[M_*D_], g_hl[M_*D_];       // final LN out, bf16 hi/lo
__device__ float g_q [M_*D_], g_k[M_*D_], g_v[M_*D_];
__device__ u16   g_cf[M_*D_];                    // attention ctx, fp16
__device__ u16   g_f16[M_*F_];                   // FFN hidden (GELU out), fp16
// transposed weights [N,K]
__device__ u16 t_q16[4*D_*D_], t_k16[4*D_*D_], t_v16[4*D_*D_], t_o16[4*D_*D_]; // fp16
__device__ u16 t_116[4*D_*F_], t_216[4*D_*F_];                                  // fp16
__device__ u16 t_wh[V_*D_], t_wl[V_*D_];                                        // bf16 hi/lo

// ---------------- small helpers ----------------
__device__ __forceinline__ u16 bfbits(float x){ __nv_bfloat16 b=__float2bfloat16(x); return *(u16*)&b; }
__device__ __forceinline__ void split2(float a, u16& h, u16& l){
    __nv_bfloat16 bh = __float2bfloat16(a);
    h = *(u16*)&bh;
    l = bfbits(a - __bfloat162float(bh));
}
__device__ __forceinline__ u16 f2h(float x){ __half h = __float2half_rn(x); return *(u16*)&h; }
__device__ __forceinline__ u32 s2u(const void* p){
    u32 a; asm("{ .reg .u64 t; cvta.to.shared.u64 t, %1; cvt.u32.u64 %0, t; }" : "=r"(a) : "l"(p));
    return a;
}
__device__ __forceinline__ u32 sw128(u32 x){ return x ^ ((x >> 3) & 0x70); }

__device__ __forceinline__ void ldsm4(u32* r, u32 a){
    asm volatile("ldmatrix.sync.aligned.m8n8.x4.shared.b16 {%0,%1,%2,%3}, [%4];"
        : "=r"(r[0]), "=r"(r[1]), "=r"(r[2]), "=r"(r[3]) : "r"(a));
}
__device__ __forceinline__ void mma_bf16(float* c, const u32* a, const u32* b){
    asm volatile("mma.sync.aligned.m16n8k16.row.col.f32.bf16.bf16.f32 "
        "{%0,%1,%2,%3}, {%4,%5,%6,%7}, {%8,%9}, {%0,%1,%2,%3};"
        : "+f"(c[0]), "+f"(c[1]), "+f"(c[2]), "+f"(c[3])
        : "r"(a[0]), "r"(a[1]), "r"(a[2]), "r"(a[3]), "r"(b[0]), "r"(b[1]));
}
__device__ __forceinline__ void mma_f16(float* c, const u32* a, const u32* b){
    asm volatile("mma.sync.aligned.m16n8k16.row.col.f32.f16.f16.f32 "
        "{%0,%1,%2,%3}, {%4,%5,%6,%7}, {%8,%9}, {%0,%1,%2,%3};"
        : "+f"(c[0]), "+f"(c[1]), "+f"(c[2]), "+f"(c[3])
        : "r"(a[0]), "r"(a[1]), "r"(a[2]), "r"(a[3]), "r"(b[0]), "r"(b[1]));
}

// ---------------- weight transpose kernels ----------------
// W[K,N] fp32 (layer = blockIdx.z) -> out [N,K]
__global__ void tcvt(const float* __restrict__ W, u16* __restrict__ oh, u16* __restrict__ ol,
                     int K, int N)
{
    __shared__ float t[32][33];
    size_t off = (size_t)blockIdx.z * K * N;
    W += off; oh += off; ol += off;
    int n0 = blockIdx.x * 32, k0 = blockIdx.y * 32;
    int tx = threadIdx.x, ty = threadIdx.y;
    for (int i = ty; i < 32; i += 8)
        t[i][tx] = W[(size_t)(k0 + i) * N + n0 + tx];
    __syncthreads();
    for (int i = ty; i < 32; i += 8) {
        float a = t[tx][i];
        size_t o = (size_t)(n0 + i) * K + k0 + tx;
        u16 h, l; split2(a, h, l);
        oh[o] = h; ol[o] = l;
    }
}
__global__ void tcvt_h(const float* __restrict__ W, u16* __restrict__ oh, int K, int N)
{
    __shared__ float t[32][33];
    size_t off = (size_t)blockIdx.z * K * N;
    W += off; oh += off;
    int n0 = blockIdx.x * 32, k0 = blockIdx.y * 32;
    int tx = threadIdx.x, ty = threadIdx.y;
    for (int i = ty; i < 32; i += 8)
        t[i][tx] = W[(size_t)(k0 + i) * N + n0 + tx];
    __syncthreads();
    for (int i = ty; i < 32; i += 8)
        oh[(size_t)(n0 + i) * K + k0 + tx] = f2h(t[tx][i]);
}

// ---------------- embedding + sinusoidal PE ----------------
__global__ void embed_kernel(const void* __restrict__ tokens,
                             const float* __restrict__ emb,
                             float* __restrict__ x)
{
    const unsigned long long* t64 = (const unsigned long long*)tokens;
    bool is64 = true;
    for (int i = 0; i < 64; i++) if (t64[i] >> 32) { is64 = false; break; }
    int row = blockIdx.x;
    int s   = row & (S_ - 1);
    long long t = is64 ? (long long)t64[row] : (long long)((const int*)tokens)[row];
    const float* e = emb + t * D_;
    float* o = x + row * D_;
    const float c1 = -9.210340371976184f / (float)D_;
    for (int c = threadIdx.x; c < D_; c += blockDim.x) {
        float div = expf((float)(c & ~1) * c1);
        float ang = (float)s * div;
        float pe  = (c & 1) ? cosf(ang) : sinf(ang);
        o[c] = e[c] * 22.62741699796952f + pe;
    }
}

// ---------------- LayerNorm. MODE 0: fp16 out; MODE 1: bf16 hi/lo out ------
template<int MODE>
__global__ void ln_kernel(const float* __restrict__ x,
                          const float* __restrict__ g,
                          const float* __restrict__ b,
                          u16* __restrict__ hh, u16* __restrict__ hl)
{
    int row = blockIdx.x;
    int t   = threadIdx.x;
    float4 v = ((const float4*)(x + row * D_))[t];
    float s  = v.x + v.y + v.z + v.w;
    float s2 = v.x*v.x + v.y*v.y + v.z*v.z + v.w*v.w;
    #pragma unroll
    for (int o = 16; o; o >>= 1) {
        s  += __shfl_xor_sync(0xffffffffu, s,  o);
        s2 += __shfl_xor_sync(0xffffffffu, s2, o);
    }
    __shared__ float ss[4], ss2[4];
    int w = t >> 5;
    if ((t & 31) == 0) { ss[w] = s; ss2[w] = s2; }
    __syncthreads();
    s  = ss[0] + ss[1] + ss[2] + ss[3];
    s2 = ss2[0] + ss2[1] + ss2[2] + ss2[3];
    float mean = s * (1.f / (float)D_);
    float var  = fmaxf(s2 * (1.f / (float)D_) - mean * mean, 0.f);
    float inv  = 1.f / (sqrtf(var) + 1e-6f);
    float4 gv = ((const float4*)g)[t];
    float4 bv = ((const float4*)b)[t];
    float o0 = gv.x * (v.x - mean) * inv + bv.x;
    float o1 = gv.y * (v.y - mean) * inv + bv.y;
    float o2 = gv.z * (v.z - mean) * inv + bv.z;
    float o3 = gv.w * (v.w - mean) * inv + bv.w;
    if (MODE == 0) {
        *(ushort4*)(hh + row * D_ + t * 4) = make_ushort4(f2h(o0), f2h(o1), f2h(o2), f2h(o3));
    } else {
        u16 h0,l0,h1,l1,h2,l2,h3,l3;
        split2(o0,h0,l0); split2(o1,h1,l1); split2(o2,h2,l2); split2(o3,h3,l3);
        *(ushort4*)(hh + row * D_ + t * 4) = make_ushort4(h0,h1,h2,h3);
        *(ushort4*)(hl + row * D_ + t * 4) = make_ushort4(l0,l1,l2,l3);
    }
}

// ================= 1-pass fp16 GEMM (in-layer) =================
// C[M,N] = A[M,K] @ B^T (B stored [N,K], fp16 both).
// EPI: 1 GELU -> fp16; 2 residual (C += v); 3 QKV scatter fp32.
#define HSMEM (2*32768)

template<int EPI, int K>
__global__ __launch_bounds__(256, 2)
void hgemm(const u16* __restrict__ A, const u16* __restrict__ B,
           const float* __restrict__ bias, float* __restrict__ C,
           u16* __restrict__ Oh, int N)
{
    extern __shared__ __align__(1024) unsigned char smem[];
    const u32 sbase = s2u(smem);
    const int tid = threadIdx.x, wid = tid >> 5, lane = tid & 31;
    const int m0 = blockIdx.x * 128, n0 = blockIdx.y * 128;
    constexpr int NC = K / 64;
    const int wm = (wid >> 1) * 32;
    const int wn = (wid & 1) * 64;

    const u16* srcs[2] = { A + (size_t)m0 * K, B + (size_t)n0 * K };

    float acc[2][8][4];
    #pragma unroll
    for (int i = 0; i < 2; i++)
        #pragma unroll
        for (int j = 0; j < 8; j++)
            #pragma unroll
            for (int q = 0; q < 4; q++) acc[i][j][q] = 0.f;

    auto prefetch = [&](int c, int buf) {
        int k0 = c * 64;
        #pragma unroll
        for (int t = 0; t < 2; t++) {
            const u16* s = srcs[t] + k0;
            u32 dst = sbase + buf * 32768 + t * 16384;
            #pragma unroll
            for (int i = 0; i < 4; i++) {
                int seg = i * 256 + tid;
                int r = seg >> 3, j = seg & 7;
                u32 a = dst + sw128(r * 128 + j * 16);
                const void* g = s + (size_t)r * K + j * 8;
                asm volatile("cp.async.cg.shared.global [%0], [%1], 16;" :: "r"(a), "l"(g));
            }
        }
        asm volatile("cp.async.commit_group;" ::: "memory");
    };

    const int grp = lane >> 3, rin = lane & 7;

    auto compute = [&](int buf) {
        u32 aB = sbase + buf * 32768, bB = aB + 16384;
        #pragma unroll
        for (int ks = 0; ks < 4; ks++) {
            u32 ah[2][4], bh[4][4];
            #pragma unroll
            for (int mb = 0; mb < 2; mb++) {
                int row = wm + mb * 16 + (grp & 1) * 8 + rin;
                ldsm4(ah[mb], aB + sw128((u32)(row * 128 + ks * 32 + (grp >> 1) * 16)));
            }
            #pragma unroll
            for (int j = 0; j < 4; j++) {
                int row = wn + j * 16 + (grp >> 1) * 8 + rin;
                ldsm4(bh[j], bB + sw128((u32)(row * 128 + ks * 32 + (grp & 1) * 16)));
            }
            #pragma unroll
            for (int mb = 0; mb < 2; mb++)
                #pragma unroll
                for (int j = 0; j < 4; j++)
                    #pragma unroll
                    for (int hf = 0; hf < 2; hf++)
                        mma_f16(acc[mb][j * 2 + hf], ah[mb], bh[j] + hf * 2);
        }
    };

    prefetch(0, 0);
    for (int c = 0; c < NC; c++) {
        int b = c & 1;
        if (c + 1 < NC) {
            prefetch(c + 1, 1 - b);
            asm volatile("cp.async.wait_group 1;" ::: "memory");
        } else {
            asm volatile("cp.async.wait_group 0;" ::: "memory");
        }
        __syncthreads();
        compute(b);
        __syncthreads();
    }

    const int rbase = lane >> 2;
    const int cbase = (lane & 3) * 2;
    #pragma unroll
    for (int mb = 0; mb < 2; mb++) {
        #pragma unroll
        for (int nb = 0; nb < 8; nb++) {
            const float* a4 = acc[mb][nb];
            int gr = m0 + wm + mb * 16 + rbase;
            int gc = n0 + wn + nb * 8 + cbase;
            float b0 = __ldg(bias + gc), b1 = __ldg(bias + gc + 1);
            float v00 = a4[0] + b0, v01 = a4[1] + b1;
            float v10 = a4[2] + b0, v11 = a4[3] + b1;
            if (EPI == 2) {
                float2 c0 = *(float2*)(C + (size_t)gr * N + gc);
                float2 c1 = *(float2*)(C + (size_t)(gr + 8) * N + gc);
                c0.x += v00; c0.y += v01; c1.x += v10; c1.y += v11;
                *(float2*)(C + (size_t)gr * N + gc)       = c0;
                *(float2*)(C + (size_t)(gr + 8) * N + gc) = c1;
            } else if (EPI == 3) {
                int h = gc >> 6, dk = gc & 63;
                size_t i0 = ((size_t)((gr >> 10) * H_ + h) * S_ + (gr & (S_ - 1))) * DK_ + dk;
                int gr8 = gr + 8;
                size_t i1 = ((size_t)((gr8 >> 10) * H_ + h) * S_ + (gr8 & (S_ - 1))) * DK_ + dk;
                *(float2*)(C + i0) = make_float2(v00, v01);
                *(float2*)(C + i1) = make_float2(v10, v11);
            } else { // EPI == 1: exact GELU -> fp16
                float g00 = 0.5f * v00 * (1.f + erff(v00 * 0.70710678118654752f));
                float g01 = 0.5f * v01 * (1.f + erff(v01 * 0.70710678118654752f));
                float g10 = 0.5f * v10 * (1.f + erff(v10 * 0.70710678118654752f));
                float g11 = 0.5f * v11 * (1.f + erff(v11 * 0.70710678118654752f));
                *(ushort2*)(Oh + (size_t)gr * N + gc)       = make_ushort2(f2h(g00), f2h(g01));
                *(ushort2*)(Oh + (size_t)(gr + 8) * N + gc) = make_ushort2(f2h(g10), f2h(g11));
            }
        }
    }
}

// ================= 3-pass split-bf16 GEMM (logits only) =================
#define GSMEM (2*65536)

template<int K>
__global__ __launch_bounds__(256, 1)
void tcgemm(const u16* __restrict__ Ah, const u16* __restrict__ Al,
            const u16* __restrict__ Bh, const u16* __restrict__ Bl,
            const float* __restrict__ bias, float* __restrict__ C, int N)
{
    extern __shared__ __align__(1024) unsigned char smem[];
    const u32 sbase = s2u(smem);
    const int tid = threadIdx.x, wid = tid >> 5, lane = tid & 31;
    const int m0 = blockIdx.x * 128, n0 = blockIdx.y * 128;
    constexpr int NC = K / 64;
    const int wm = (wid >> 1) * 32;
    const int wn = (wid & 1) * 64;

    const u16* srcs[4] = { Ah + (size_t)m0 * K, Al + (size_t)m0 * K,
                           Bh + (size_t)n0 * K, Bl + (size_t)n0 * K };

    float acc[2][8][4];
    #pragma unroll
    for (int i = 0; i < 2; i++)
        #pragma unroll
        for (int j = 0; j < 8; j++)
            #pragma unroll
            for (int q = 0; q < 4; q++) acc[i][j][q] = 0.f;

    auto prefetch = [&](int c, int buf) {
        int k0 = c * 64;
        #pragma unroll
        for (int t = 0; t < 4; t++) {
            const u16* s = srcs[t] + k0;
            u32 dst = sbase + buf * 65536 + t * 16384;
            #pragma unroll
            for (int i = 0; i < 4; i++) {
                int seg = i * 256 + tid;
                int r = seg >> 3, j = seg & 7;
                u32 a = dst + sw128(r * 128 + j * 16);
                const void* g = s + (size_t)r * K + j * 8;
                asm volatile("cp.async.cg.shared.global [%0], [%1], 16;" :: "r"(a), "l"(g));
            }
        }
        asm volatile("cp.async.commit_group;" ::: "memory");
    };

    const int grp = lane >> 3, rin = lane & 7;

    auto compute = [&](int buf) {
        u32 base = sbase + buf * 65536;
        u32 aHb = base, aLb = base + 16384, bHb = base + 32768, bLb = base + 49152;
        #pragma unroll
        for (int ks = 0; ks < 4; ks++) {
            u32 ah[2][4], al[2][4], bh[4][4], bl[4][4];
            #pragma unroll
            for (int mb = 0; mb < 2; mb++) {
                int row = wm + mb * 16 + (grp & 1) * 8 + rin;
                u32 off = sw128((u32)(row * 128 + ks * 32 + (grp >> 1) * 16));
                ldsm4(ah[mb], aHb + off);
                ldsm4(al[mb], aLb + off);
            }
            #pragma unroll
            for (int j = 0; j < 4; j++) {
                int row = wn + j * 16 + (grp >> 1) * 8 + rin;
                u32 off = sw128((u32)(row * 128 + ks * 32 + (grp & 1) * 16));
                ldsm4(bh[j], bHb + off);
                ldsm4(bl[j], bLb + off);
            }
            #pragma unroll
            for (int mb = 0; mb < 2; mb++)
                #pragma unroll
                for (int j = 0; j < 4; j++)
                    #pragma unroll
                    for (int hf = 0; hf < 2; hf++) {
                        int nb = j * 2 + hf;
                        mma_bf16(acc[mb][nb], ah[mb], bh[j] + hf * 2);
                        mma_bf16(acc[mb][nb], ah[mb], bl[j] + hf * 2);
                        mma_bf16(acc[mb][nb], al[mb], bh[j] + hf * 2);
                    }
        }
    };

    prefetch(0, 0);
    for (int c = 0; c < NC; c++) {
        int b = c & 1;
        if (c + 1 < NC) {
            prefetch(c + 1, 1 - b);
            asm volatile("cp.async.wait_group 1;" ::: "memory");
        } else {
            asm volatile("cp.async.wait_group 0;" ::: "memory");
        }
        __syncthreads();
        compute(b);
        __syncthreads();
    }

    const int rbase = lane >> 2;
    const int cbase = (lane & 3) * 2;
    #pragma unroll
    for (int mb = 0; mb < 2; mb++) {
        #pragma unroll
        for (int nb = 0; nb < 8; nb++) {
            const float* a4 = acc[mb][nb];
            int gr = m0 + wm + mb * 16 + rbase;
            int gc = n0 + wn + nb * 8 + cbase;
            float b0 = __ldg(bias + gc), b1 = __ldg(bias + gc + 1);
            *(float2*)(C + (size_t)gr * N + gc)       = make_float2(a4[0] + b0, a4[1] + b1);
            *(float2*)(C + (size_t)(gr + 8) * N + gc) = make_float2(a4[2] + b0, a4[3] + b1);
        }
    }
}

// ---------------- flash-style causal attention (fp32) -> ctx fp16 ----------------
__global__ __launch_bounds__(256)
void attn_kernel(const float* __restrict__ q, const float* __restrict__ k,
                 const float* __restrict__ v, u16* __restrict__ cf)
{
    extern __shared__ float sm[];
    float* Qs = sm;
    float* Ks = sm + 4160;
    float* Ps = sm + 8320;
    int qb = blockIdx.x, bh = blockIdx.y;
    int b = bh >> 3, h = bh & 7;
    const float* qh = q + (long long)bh * S_ * DK_;
    const float* kh = k + (long long)bh * S_ * DK_;
    const float* vh = v + (long long)bh * S_ * DK_;
    int tid = threadIdx.x;
    int rr = tid >> 3;
    int c8 = tid & 7;

    for (int i = tid; i < 4096; i += 256) {
        int r = i >> 6, c = i & 63;
        Qs[r * 65 + c] = qh[(qb * 64 + r) * 64 + c];
    }

    float m0 = -1e30f, m1 = -1e30f, l0 = 0.f, l1 = 0.f;
    float acc0[8], acc1[8];
    #pragma unroll
    for (int i = 0; i < 8; i++) { acc0[i] = 0.f; acc1[i] = 0.f; }
    int gq0 = qb * 64 + rr, gq1 = gq0 + 32;

    for (int kt = 0; kt <= qb; kt++) {
        __syncthreads();
        for (int i = tid; i < 4096; i += 256) {
            int r = i >> 6, c = i & 63;
            Ks[r * 65 + c] = kh[(kt * 64 + r) * 64 + c];
        }
        __syncthreads();

        float s0[8], s1[8];
        #pragma unroll
        for (int i = 0; i < 8; i++) { s0[i] = 0.f; s1[i] = 0.f; }
        #pragma unroll 8
        for (int d = 0; d < 64; d++) {
            float q0 = Qs[rr * 65 + d];
            float q1 = Qs[(rr + 32) * 65 + d];
            #pragma unroll
            for (int i = 0; i < 8; i++) {
                float kv = Ks[(c8 + 8 * i) * 65 + d];
                s0[i] += q0 * kv;
                s1[i] += q1 * kv;
            }
        }
        float mt0 = -1e30f, mt1 = -1e30f;
        #pragma unroll
        for (int i = 0; i < 8; i++) {
            int gk = kt * 64 + c8 + 8 * i;
            s0[i] = (gk <= gq0) ? s0[i] * 0.125f : -1e9f;
            s1[i] = (gk <= gq1) ? s1[i] * 0.125f : -1e9f;
            mt0 = fmaxf(mt0, s0[i]);
            mt1 = fmaxf(mt1, s1[i]);
        }
        #pragma unroll
        for (int o = 1; o < 8; o <<= 1) {
            mt0 = fmaxf(mt0, __shfl_xor_sync(0xffffffffu, mt0, o));
            mt1 = fmaxf(mt1, __shfl_xor_sync(0xffffffffu, mt1, o));
        }
        float mn0 = fmaxf(m0, mt0), mn1 = fmaxf(m1, mt1);
        float f0 = __expf(m0 - mn0), f1 = __expf(m1 - mn1);
        float lt0 = 0.f, lt1 = 0.f;
        #pragma unroll
        for (int i = 0; i < 8; i++) {
            s0[i] = __expf(s0[i] - mn0); lt0 += s0[i];
            s1[i] = __expf(s1[i] - mn1); lt1 += s1[i];
        }
        #pragma unroll
        for (int o = 1; o < 8; o <<= 1) {
            lt0 += __shfl_xor_sync(0xffffffffu, lt0, o);
            lt1 += __shfl_xor_sync(0xffffffffu, lt1, o);
        }
        l0 = l0 * f0 + lt0;  l1 = l1 * f1 + lt1;
        m0 = mn0;            m1 = mn1;
        #pragma unroll
        for (int i = 0; i < 8; i++) { acc0[i] *= f0; acc1[i] *= f1; }
        #pragma unroll
        for (int i = 0; i < 8; i++) {
            Ps[rr * 65 + c8 + 8 * i]        = s0[i];
            Ps[(rr + 32) * 65 + c8 + 8 * i] = s1[i];
        }
        __syncthreads();
        for (int i = tid; i < 4096; i += 256) {
            int r = i >> 6, c = i & 63;
            Ks[r * 65 + c] = vh[(kt * 64 + r) * 64 + c];
        }
        __syncthreads();
        #pragma unroll 8
        for (int j = 0; j < 64; j++) {
            float p0 = Ps[rr * 65 + j];
            float p1 = Ps[(rr + 32) * 65 + j];
            #pragma unroll
            for (int i = 0; i < 8; i++) {
                float vv = Ks[j * 65 + c8 + 8 * i];
                acc0[i] += p0 * vv;
                acc1[i] += p1 * vv;
            }
        }
    }

    float r0 = 1.f / l0, r1 = 1.f / l1;
    long long base0 = (long long)(b * S_ + qb * 64 + rr) * D_ + h * DK_ + c8;
    long long base1 = base0 + 32LL * D_;
    #pragma unroll
    for (int i = 0; i < 8; i++) {
        cf[base0 + 8 * i] = f2h(acc0[i] * r0);
        cf[base1 + 8 * i] = f2h(acc1[i] * r1);
    }
}

// ---------------- launch ----------------
extern "C" void kernel_launch(void* const* d_in, const int* in_sizes, int n_in,
                              void* d_out, int out_size)
{
    const void*  tok     = d_in[0];
    const float* tok_emb = (const float*)d_in[1];
    const float* gamma1  = (const float*)d_in[2];
    const float* beta1   = (const float*)d_in[3];
    const float* wq      = (const float*)d_in[4];
    const float* bq      = (const float*)d_in[5];
    const float* wk      = (const float*)d_in[6];
    const float* bk      = (const float*)d_in[7];
    const float* wv      = (const float*)d_in[8];
    const float* bv      = (const float*)d_in[9];
    const float* wo      = (const float*)d_in[10];
    const float* bo      = (const float*)d_in[11];
    const float* gamma2  = (const float*)d_in[12];
    const float* beta2   = (const float*)d_in[13];
    const float* w1      = (const float*)d_in[14];
    const float* b1      = (const float*)d_in[15];
    const float* w2      = (const float*)d_in[16];
    const float* b2      = (const float*)d_in[17];
    const float* gamma_f = (const float*)d_in[18];
    const float* beta_f  = (const float*)d_in[19];
    const float* w_out   = (const float*)d_in[20];
    const float* b_out   = (const float*)d_in[21];
    float* out = (float*)d_out;

    float *x, *q, *k, *v;
    u16 *hf, *hh, *hl, *cf, *f16;
    u16 *q16, *k16, *v16, *o16, *w116, *w216, *wvh, *wvl;
    cudaGetSymbolAddress((void**)&x, g_x);
    cudaGetSymbolAddress((void**)&q, g_q);   cudaGetSymbolAddress((void**)&k, g_k);
    cudaGetSymbolAddress((void**)&v, g_v);
    cudaGetSymbolAddress((void**)&hf, g_hf);
    cudaGetSymbolAddress((void**)&hh, g_hh); cudaGetSymbolAddress((void**)&hl, g_hl);
    cudaGetSymbolAddress((void**)&cf, g_cf); cudaGetSymbolAddress((void**)&f16, g_f16);
    cudaGetSymbolAddress((void**)&q16, t_q16); cudaGetSymbolAddress((void**)&k16, t_k16);
    cudaGetSymbolAddress((void**)&v16, t_v16); cudaGetSymbolAddress((void**)&o16, t_o16);
    cudaGetSymbolAddress((void**)&w116, t_116); cudaGetSymbolAddress((void**)&w216, t_216);
    cudaGetSymbolAddress((void**)&wvh, t_wh); cudaGetSymbolAddress((void**)&wvl, t_wl);

    cudaFuncSetAttribute(attn_kernel, cudaFuncAttributeMaxDynamicSharedMemorySize, 49920);
    cudaFuncSetAttribute(hgemm<1,512>,  cudaFuncAttributeMaxDynamicSharedMemorySize, HSMEM);
    cudaFuncSetAttribute(hgemm<2,512>,  cudaFuncAttributeMaxDynamicSharedMemorySize, HSMEM);
    cudaFuncSetAttribute(hgemm<2,2048>, cudaFuncAttributeMaxDynamicSharedMemorySize, HSMEM);
    cudaFuncSetAttribute(hgemm<3,512>,  cudaFuncAttributeMaxDynamicSharedMemorySize, HSMEM);
    cudaFuncSetAttribute(tcgemm<512>,   cudaFuncAttributeMaxDynamicSharedMemorySize, GSMEM);

    // weight prep
    dim3 tb(32, 8);
    tcvt_h<<<dim3(16, 16, 4),  tb>>>(wq, q16, D_, D_);
    tcvt_h<<<dim3(16, 16, 4),  tb>>>(wk, k16, D_, D_);
    tcvt_h<<<dim3(16, 16, 4),  tb>>>(wv, v16, D_, D_);
    tcvt_h<<<dim3(16, 16, 4),  tb>>>(wo, o16, D_, D_);
    tcvt_h<<<dim3(64, 16, 4),  tb>>>(w1, w116, D_, F_);
    tcvt_h<<<dim3(16, 64, 4),  tb>>>(w2, w216, F_, D_);
    tcvt<<<dim3(1000, 16, 1), tb>>>(w_out, wvh, wvl, D_, V_);

    embed_kernel<<<M_, 256>>>(tok, tok_emb, x);

    dim3 gD(32, 4);      // N=512
    dim3 gF(32, 16);     // N=2048
    dim3 gV(32, 250);    // N=32000

    for (int l = 0; l < 4; l++) {
        size_t od = (size_t)l * D_ * D_, of = (size_t)l * D_ * F_;
        ln_kernel<0><<<M_, 128>>>(x, gamma1 + l*D_, beta1 + l*D_, hf, 0);
        hgemm<3,512><<<gD, 256, HSMEM>>>(hf, q16+od, bq + l*D_, q, 0, D_);
        hgemm<3,512><<<gD, 256, HSMEM>>>(hf, k16+od, bk + l*D_, k, 0, D_);
        hgemm<3,512><<<gD, 256, HSMEM>>>(hf, v16+od, bv + l*D_, v, 0, D_);
        attn_kernel<<<dim3(S_/64, B_*H_), 256, 49920>>>(q, k, v, cf);
        hgemm<2,512><<<gD, 256, HSMEM>>>(cf, o16+od, bo + l*D_, x, 0, D_);
        ln_kernel<0><<<M_, 128>>>(x, gamma2 + l*D_, beta2 + l*D_, hf, 0);
        hgemm<1,512><<<gF, 256, HSMEM>>>(hf, w116+of, b1 + l*F_, 0, f16, F_);
        hgemm<2,2048><<<gD, 256, HSMEM>>>(f16, w216+of, b2 + l*D_, x, 0, D_);
    }
    ln_kernel<1><<<M_, 128>>>(x, gamma_f, beta_f, hh, hl);
    tcgemm<512><<<gV, 256, GSMEM>>>(hh, hl, wvh, wvl, b_out, out, V_);
}

// round 13
// speedup vs baseline: 2.0175x; 2.0175x over previous
#include <cuda_runtime.h>
#include <cuda_fp16.h>
#include <math.h>

#define B_   4
#define S_   1024
#define D_   512
#define H_   8
#define DK_  64
#define F_   2048
#define V_   32000
#define M_   4096

typedef unsigned short u16;
typedef unsigned int   u32;
typedef unsigned long long u64;

// ---------------- scratch (device globals: allocation-free) ----------------
__device__ float g_x [M_*D_];                    // residual stream fp32
__device__ u16   g_hf[M_*D_];                    // LN out, fp16
__device__ u16   g_q16[M_*D_], g_k16[M_*D_], g_v16[M_*D_];  // [B,H,S,DK] fp16
__device__ u16   g_cf[M_*D_];                    // attention ctx, fp16
__device__ u16   g_f16[M_*F_];                   // FFN hidden (GELU out), fp16
// transposed weights [N,K] fp16
__device__ u16 t_q16[4*D_*D_], t_k16[4*D_*D_], t_v16[4*D_*D_], t_o16[4*D_*D_];
__device__ u16 t_116[4*D_*F_], t_216[4*D_*F_];
__device__ u16 t_wh[V_*D_], t_wl[V_*D_];         // w_out^T fp16 hi + 1024-scaled lo

// ---------------- small helpers ----------------
__device__ __forceinline__ u16 f2h(float x){ __half h = __float2half_rn(x); return *(u16*)&h; }
__device__ __forceinline__ void split2h(float a, u16& h, u16& l){
    __half hh = __float2half_rn(a);
    h = *(u16*)&hh;
    l = f2h((a - __half2float(hh)) * 1024.f);
}
__device__ __forceinline__ u32 packh2(float a, float b){
    __half2 h = __floats2half2_rn(a, b);
    return *(u32*)&h;
}
__device__ __forceinline__ u32 s2u(const void* p){
    u32 a; asm("{ .reg .u64 t; cvta.to.shared.u64 t, %1; cvt.u32.u64 %0, t; }" : "=r"(a) : "l"(p));
    return a;
}
__device__ __forceinline__ u32 sw128(u32 x){ return x ^ ((x >> 3) & 0x70); }

__device__ __forceinline__ void ldsm4(u32* r, u32 a){
    asm volatile("ldmatrix.sync.aligned.m8n8.x4.shared.b16 {%0,%1,%2,%3}, [%4];"
        : "=r"(r[0]), "=r"(r[1]), "=r"(r[2]), "=r"(r[3]) : "r"(a));
}
__device__ __forceinline__ void ldsm4t(u32* r, u32 a){
    asm volatile("ldmatrix.sync.aligned.m8n8.x4.trans.shared.b16 {%0,%1,%2,%3}, [%4];"
        : "=r"(r[0]), "=r"(r[1]), "=r"(r[2]), "=r"(r[3]) : "r"(a));
}
__device__ __forceinline__ void mma_f16(float* c, const u32* a, const u32* b){
    asm volatile("mma.sync.aligned.m16n8k16.row.col.f32.f16.f16.f32 "
        "{%0,%1,%2,%3}, {%4,%5,%6,%7}, {%8,%9}, {%0,%1,%2,%3};"
        : "+f"(c[0]), "+f"(c[1]), "+f"(c[2]), "+f"(c[3])
        : "r"(a[0]), "r"(a[1]), "r"(a[2]), "r"(a[3]), "r"(b[0]), "r"(b[1]));
}
#define CPA16(dst, src) asm volatile("cp.async.cg.shared.global [%0], [%1], 16;" :: "r"(dst), "l"(src))
#define CPCOMMIT()      asm volatile("cp.async.commit_group;" ::: "memory")
#define CPWAIT(n)       asm volatile("cp.async.wait_group %0;" :: "n"(n) : "memory")

// ---------------- weight transpose kernels ----------------
__global__ void tcvt_h(const float* __restrict__ W, u16* __restrict__ oh, int K, int N)
{
    __shared__ float t[32][33];
    size_t off = (size_t)blockIdx.z * K * N;
    W += off; oh += off;
    int n0 = blockIdx.x * 32, k0 = blockIdx.y * 32;
    int tx = threadIdx.x, ty = threadIdx.y;
    for (int i = ty; i < 32; i += 8)
        t[i][tx] = W[(size_t)(k0 + i) * N + n0 + tx];
    __syncthreads();
    for (int i = ty; i < 32; i += 8)
        oh[(size_t)(n0 + i) * K + k0 + tx] = f2h(t[tx][i]);
}
__global__ void tcvt_h2(const float* __restrict__ W, u16* __restrict__ oh, u16* __restrict__ ol,
                        int K, int N)
{
    __shared__ float t[32][33];
    int n0 = blockIdx.x * 32, k0 = blockIdx.y * 32;
    int tx = threadIdx.x, ty = threadIdx.y;
    for (int i = ty; i < 32; i += 8)
        t[i][tx] = W[(size_t)(k0 + i) * N + n0 + tx];
    __syncthreads();
    for (int i = ty; i < 32; i += 8) {
        size_t o = (size_t)(n0 + i) * K + k0 + tx;
        u16 h, l; split2h(t[tx][i], h, l);
        oh[o] = h; ol[o] = l;
    }
}

// ---------------- embedding + sinusoidal PE ----------------
__global__ void embed_kernel(const void* __restrict__ tokens,
                             const float* __restrict__ emb,
                             float* __restrict__ x)
{
    const unsigned long long* t64 = (const unsigned long long*)tokens;
    bool is64 = true;
    for (int i = 0; i < 64; i++) if (t64[i] >> 32) { is64 = false; break; }
    int row = blockIdx.x;
    int s   = row & (S_ - 1);
    long long t = is64 ? (long long)t64[row] : (long long)((const int*)tokens)[row];
    const float* e = emb + t * D_;
    float* o = x + row * D_;
    const float c1 = -9.210340371976184f / (float)D_;
    for (int c = threadIdx.x; c < D_; c += blockDim.x) {
        float div = expf((float)(c & ~1) * c1);
        float ang = (float)s * div;
        float pe  = (c & 1) ? cosf(ang) : sinf(ang);
        o[c] = e[c] * 22.62741699796952f + pe;
    }
}

// ---------------- LayerNorm -> fp16 ----------------
__global__ void ln_kernel(const float* __restrict__ x,
                          const float* __restrict__ g,
                          const float* __restrict__ b,
                          u16* __restrict__ hf)
{
    int row = blockIdx.x;
    int t   = threadIdx.x;
    float4 v = ((const float4*)(x + row * D_))[t];
    float s  = v.x + v.y + v.z + v.w;
    float s2 = v.x*v.x + v.y*v.y + v.z*v.z + v.w*v.w;
    #pragma unroll
    for (int o = 16; o; o >>= 1) {
        s  += __shfl_xor_sync(0xffffffffu, s,  o);
        s2 += __shfl_xor_sync(0xffffffffu, s2, o);
    }
    __shared__ float ss[4], ss2[4];
    int w = t >> 5;
    if ((t & 31) == 0) { ss[w] = s; ss2[w] = s2; }
    __syncthreads();
    s  = ss[0] + ss[1] + ss[2] + ss[3];
    s2 = ss2[0] + ss2[1] + ss2[2] + ss2[3];
    float mean = s * (1.f / (float)D_);
    float var  = fmaxf(s2 * (1.f / (float)D_) - mean * mean, 0.f);
    float inv  = 1.f / (sqrtf(var) + 1e-6f);
    float4 gv = ((const float4*)g)[t];
    float4 bv = ((const float4*)b)[t];
    float o0 = gv.x * (v.x - mean) * inv + bv.x;
    float o1 = gv.y * (v.y - mean) * inv + bv.y;
    float o2 = gv.z * (v.z - mean) * inv + bv.z;
    float o3 = gv.w * (v.w - mean) * inv + bv.w;
    *(ushort4*)(hf + row * D_ + t * 4) = make_ushort4(f2h(o0), f2h(o1), f2h(o2), f2h(o3));
}

// ================= 1-pass fp16 GEMM (in-layer) =================
// C[M,N] = A[M,K] @ B^T (B stored [N,K], fp16 both).
// EPI: 1 GELU -> fp16; 2 residual (C += v); 3 QKV scatter fp16 [B,H,S,DK].
#define HSMEM (2*32768)

template<int EPI, int K>
__global__ __launch_bounds__(256, 2)
void hgemm(const u16* __restrict__ A, const u16* __restrict__ B,
           const float* __restrict__ bias, float* __restrict__ C,
           u16* __restrict__ Oh, int N)
{
    extern __shared__ __align__(1024) unsigned char smem[];
    const u32 sbase = s2u(smem);
    const int tid = threadIdx.x, wid = tid >> 5, lane = tid & 31;
    const int m0 = blockIdx.x * 128, n0 = blockIdx.y * 128;
    constexpr int NC = K / 64;
    const int wm = (wid >> 1) * 32;
    const int wn = (wid & 1) * 64;

    const u16* srcs[2] = { A + (size_t)m0 * K, B + (size_t)n0 * K };

    float acc[2][8][4];
    #pragma unroll
    for (int i = 0; i < 2; i++)
        #pragma unroll
        for (int j = 0; j < 8; j++)
            #pragma unroll
            for (int q = 0; q < 4; q++) acc[i][j][q] = 0.f;

    auto prefetch = [&](int c, int buf) {
        int k0 = c * 64;
        #pragma unroll
        for (int t = 0; t < 2; t++) {
            const u16* s = srcs[t] + k0;
            u32 dst = sbase + buf * 32768 + t * 16384;
            #pragma unroll
            for (int i = 0; i < 4; i++) {
                int seg = i * 256 + tid;
                int r = seg >> 3, j = seg & 7;
                CPA16(dst + sw128(r * 128 + j * 16), s + (size_t)r * K + j * 8);
            }
        }
        CPCOMMIT();
    };

    const int grp = lane >> 3, rin = lane & 7;

    auto compute = [&](int buf) {
        u32 aB = sbase + buf * 32768, bB = aB + 16384;
        #pragma unroll
        for (int ks = 0; ks < 4; ks++) {
            u32 ah[2][4], bh[4][4];
            #pragma unroll
            for (int mb = 0; mb < 2; mb++) {
                int row = wm + mb * 16 + (grp & 1) * 8 + rin;
                ldsm4(ah[mb], aB + sw128((u32)(row * 128 + ks * 32 + (grp >> 1) * 16)));
            }
            #pragma unroll
            for (int j = 0; j < 4; j++) {
                int row = wn + j * 16 + (grp >> 1) * 8 + rin;
                ldsm4(bh[j], bB + sw128((u32)(row * 128 + ks * 32 + (grp & 1) * 16)));
            }
            #pragma unroll
            for (int mb = 0; mb < 2; mb++)
                #pragma unroll
                for (int j = 0; j < 4; j++)
                    #pragma unroll
                    for (int hf = 0; hf < 2; hf++)
                        mma_f16(acc[mb][j * 2 + hf], ah[mb], bh[j] + hf * 2);
        }
    };

    prefetch(0, 0);
    for (int c = 0; c < NC; c++) {
        int b = c & 1;
        if (c + 1 < NC) {
            prefetch(c + 1, 1 - b);
            CPWAIT(1);
        } else {
            CPWAIT(0);
        }
        __syncthreads();
        compute(b);
        __syncthreads();
    }

    const int rbase = lane >> 2;
    const int cbase = (lane & 3) * 2;
    #pragma unroll
    for (int mb = 0; mb < 2; mb++) {
        #pragma unroll
        for (int nb = 0; nb < 8; nb++) {
            const float* a4 = acc[mb][nb];
            int gr = m0 + wm + mb * 16 + rbase;
            int gc = n0 + wn + nb * 8 + cbase;
            float b0 = __ldg(bias + gc), b1 = __ldg(bias + gc + 1);
            float v00 = a4[0] + b0, v01 = a4[1] + b1;
            float v10 = a4[2] + b0, v11 = a4[3] + b1;
            if (EPI == 2) {
                float2 c0 = *(float2*)(C + (size_t)gr * N + gc);
                float2 c1 = *(float2*)(C + (size_t)(gr + 8) * N + gc);
                c0.x += v00; c0.y += v01; c1.x += v10; c1.y += v11;
                *(float2*)(C + (size_t)gr * N + gc)       = c0;
                *(float2*)(C + (size_t)(gr + 8) * N + gc) = c1;
            } else if (EPI == 3) {
                int h = gc >> 6, dk = gc & 63;
                size_t i0 = ((size_t)((gr >> 10) * H_ + h) * S_ + (gr & (S_ - 1))) * DK_ + dk;
                int gr8 = gr + 8;
                size_t i1 = ((size_t)((gr8 >> 10) * H_ + h) * S_ + (gr8 & (S_ - 1))) * DK_ + dk;
                *(ushort2*)(Oh + i0) = make_ushort2(f2h(v00), f2h(v01));
                *(ushort2*)(Oh + i1) = make_ushort2(f2h(v10), f2h(v11));
            } else { // EPI == 1: exact GELU -> fp16
                float g00 = 0.5f * v00 * (1.f + erff(v00 * 0.70710678118654752f));
                float g01 = 0.5f * v01 * (1.f + erff(v01 * 0.70710678118654752f));
                float g10 = 0.5f * v10 * (1.f + erff(v10 * 0.70710678118654752f));
                float g11 = 0.5f * v11 * (1.f + erff(v11 * 0.70710678118654752f));
                *(ushort2*)(Oh + (size_t)gr * N + gc)       = make_ushort2(f2h(g00), f2h(g01));
                *(ushort2*)(Oh + (size_t)(gr + 8) * N + gc) = make_ushort2(f2h(g10), f2h(g11));
            }
        }
    }
}

// ================= 2-pass fp16 GEMM (logits): A·Bh + A·Bl/1024 =================
#define VSMEM (2*49152)

__global__ __launch_bounds__(256, 1)
void vgemm(const u16* __restrict__ A, const u16* __restrict__ Bh, const u16* __restrict__ Bl,
           const float* __restrict__ bias, float* __restrict__ C, int N)
{
    extern __shared__ __align__(1024) unsigned char smem[];
    const u32 sbase = s2u(smem);
    const int tid = threadIdx.x, wid = tid >> 5, lane = tid & 31;
    const int m0 = blockIdx.x * 128, n0 = blockIdx.y * 128;
    constexpr int K = 512, NC = K / 64;
    const int wm = (wid >> 1) * 32;
    const int wn = (wid & 1) * 64;

    const u16* srcs[3] = { A + (size_t)m0 * K, Bh + (size_t)n0 * K, Bl + (size_t)n0 * K };

    float acch[2][8][4], accl[2][8][4];
    #pragma unroll
    for (int i = 0; i < 2; i++)
        #pragma unroll
        for (int j = 0; j < 8; j++)
            #pragma unroll
            for (int q = 0; q < 4; q++) { acch[i][j][q] = 0.f; accl[i][j][q] = 0.f; }

    auto prefetch = [&](int c, int buf) {
        int k0 = c * 64;
        #pragma unroll
        for (int t = 0; t < 3; t++) {
            const u16* s = srcs[t] + k0;
            u32 dst = sbase + buf * 49152 + t * 16384;
            #pragma unroll
            for (int i = 0; i < 4; i++) {
                int seg = i * 256 + tid;
                int r = seg >> 3, j = seg & 7;
                CPA16(dst + sw128(r * 128 + j * 16), s + (size_t)r * K + j * 8);
            }
        }
        CPCOMMIT();
    };

    const int grp = lane >> 3, rin = lane & 7;

    auto compute = [&](int buf) {
        u32 aB = sbase + buf * 49152, hB = aB + 16384, lB = aB + 32768;
        #pragma unroll
        for (int ks = 0; ks < 4; ks++) {
            u32 ah[2][4], bh[4][4], bl[4][4];
            #pragma unroll
            for (int mb = 0; mb < 2; mb++) {
                int row = wm + mb * 16 + (grp & 1) * 8 + rin;
                ldsm4(ah[mb], aB + sw128((u32)(row * 128 + ks * 32 + (grp >> 1) * 16)));
            }
            #pragma unroll
            for (int j = 0; j < 4; j++) {
                int row = wn + j * 16 + (grp >> 1) * 8 + rin;
                u32 off = sw128((u32)(row * 128 + ks * 32 + (grp & 1) * 16));
                ldsm4(bh[j], hB + off);
                ldsm4(bl[j], lB + off);
            }
            #pragma unroll
            for (int mb = 0; mb < 2; mb++)
                #pragma unroll
                for (int j = 0; j < 4; j++)
                    #pragma unroll
                    for (int hf = 0; hf < 2; hf++) {
                        mma_f16(acch[mb][j * 2 + hf], ah[mb], bh[j] + hf * 2);
                        mma_f16(accl[mb][j * 2 + hf], ah[mb], bl[j] + hf * 2);
                    }
        }
    };

    prefetch(0, 0);
    for (int c = 0; c < NC; c++) {
        int b = c & 1;
        if (c + 1 < NC) {
            prefetch(c + 1, 1 - b);
            CPWAIT(1);
        } else {
            CPWAIT(0);
        }
        __syncthreads();
        compute(b);
        __syncthreads();
    }

    const int rbase = lane >> 2;
    const int cbase = (lane & 3) * 2;
    const float is = 1.f / 1024.f;
    #pragma unroll
    for (int mb = 0; mb < 2; mb++) {
        #pragma unroll
        for (int nb = 0; nb < 8; nb++) {
            int gr = m0 + wm + mb * 16 + rbase;
            int gc = n0 + wn + nb * 8 + cbase;
            float b0 = __ldg(bias + gc), b1 = __ldg(bias + gc + 1);
            float v00 = acch[mb][nb][0] + accl[mb][nb][0] * is + b0;
            float v01 = acch[mb][nb][1] + accl[mb][nb][1] * is + b1;
            float v10 = acch[mb][nb][2] + accl[mb][nb][2] * is + b0;
            float v11 = acch[mb][nb][3] + accl[mb][nb][3] * is + b1;
            *(float2*)(C + (size_t)gr * N + gc)       = make_float2(v00, v01);
            *(float2*)(C + (size_t)(gr + 8) * N + gc) = make_float2(v10, v11);
        }
    }
}

// ================= tensor-core flash attention =================
// 4 warps, 64-query tile per CTA, 64-key tiles, fp16 QK/PV mma, fp32 softmax.
#define ATT_SMEM (8192 + 2*16384)

__global__ __launch_bounds__(128)
void attn_kernel(const u16* __restrict__ q, const u16* __restrict__ k,
                 const u16* __restrict__ v, u16* __restrict__ cf)
{
    extern __shared__ __align__(1024) unsigned char smraw[];
    const u32 sQ = s2u(smraw);
    int qb = blockIdx.x, bh = blockIdx.y;
    int b = bh >> 3, h = bh & 7;
    const u16* qg = q + (size_t)bh * S_ * DK_;
    const u16* kg = k + (size_t)bh * S_ * DK_;
    const u16* vg = v + (size_t)bh * S_ * DK_;
    const int tid = threadIdx.x, wid = tid >> 5, lane = tid & 31;
    const int g_ = lane >> 3, rw = lane & 7;

    // Q tile: 64 rows x 128B, swizzled
    #pragma unroll
    for (int i = 0; i < 4; i++) {
        int seg = i * 128 + tid;
        int r = seg >> 3, j = seg & 7;
        CPA16(sQ + sw128(r * 128 + j * 16), qg + (size_t)(qb * 64 + r) * DK_ + j * 8);
    }
    CPCOMMIT();

    auto ldkv = [&](int kt, int buf) {
        u32 base = sQ + 8192 + buf * 16384;
        #pragma unroll
        for (int i = 0; i < 4; i++) {
            int seg = i * 128 + tid;
            int r = seg >> 3, j = seg & 7;
            u32 off = sw128(r * 128 + j * 16);
            CPA16(base + off,        kg + (size_t)(kt * 64 + r) * DK_ + j * 8);
            CPA16(base + 8192 + off, vg + (size_t)(kt * 64 + r) * DK_ + j * 8);
        }
        CPCOMMIT();
    };
    ldkv(0, 0);

    CPWAIT(1);            // Q done
    __syncthreads();
    u32 qf[4][4];
    #pragma unroll
    for (int ks = 0; ks < 4; ks++) {
        int row = wid * 16 + (g_ & 1) * 8 + rw;
        ldsm4(qf[ks], sQ + sw128((u32)(row * 128 + ks * 32 + (g_ >> 1) * 16)));
    }

    float m0 = -1e30f, m1 = -1e30f, l0 = 0.f, l1 = 0.f;
    float o[8][4];
    #pragma unroll
    for (int nb = 0; nb < 8; nb++)
        #pragma unroll
        for (int qq = 0; qq < 4; qq++) o[nb][qq] = 0.f;
    const int gq0 = qb * 64 + wid * 16 + (lane >> 2);   // row for c0,c1; c2,c3 at +8

    for (int kt = 0; kt <= qb; kt++) {
        int buf = kt & 1;
        if (kt < qb) { ldkv(kt + 1, 1 - buf); CPWAIT(1); }
        else         { CPWAIT(0); }
        __syncthreads();
        u32 sK = sQ + 8192 + buf * 16384, sV = sK + 8192;

        // ---- S = Q K^T ----
        float s[8][4];
        #pragma unroll
        for (int nb = 0; nb < 8; nb++)
            #pragma unroll
            for (int qq = 0; qq < 4; qq++) s[nb][qq] = 0.f;
        #pragma unroll
        for (int ks = 0; ks < 4; ks++) {
            #pragma unroll
            for (int kp = 0; kp < 4; kp++) {
                u32 kf[4];
                int row = kp * 16 + (g_ >> 1) * 8 + rw;
                ldsm4(kf, sK + sw128((u32)(row * 128 + ks * 32 + (g_ & 1) * 16)));
                mma_f16(s[kp * 2],     qf[ks], kf);
                mma_f16(s[kp * 2 + 1], qf[ks], kf + 2);
            }
        }

        // ---- scale + causal mask (diagonal tile only) ----
        if (kt == qb) {
            #pragma unroll
            for (int nb = 0; nb < 8; nb++) {
                int gk = kt * 64 + nb * 8 + (lane & 3) * 2;
                s[nb][0] = (gk     <= gq0)     ? s[nb][0] * 0.125f : -1e9f;
                s[nb][1] = (gk + 1 <= gq0)     ? s[nb][1] * 0.125f : -1e9f;
                s[nb][2] = (gk     <= gq0 + 8) ? s[nb][2] * 0.125f : -1e9f;
                s[nb][3] = (gk + 1 <= gq0 + 8) ? s[nb][3] * 0.125f : -1e9f;
            }
        } else {
            #pragma unroll
            for (int nb = 0; nb < 8; nb++)
                #pragma unroll
                for (int qq = 0; qq < 4; qq++) s[nb][qq] *= 0.125f;
        }

        // ---- online softmax ----
        float mt0 = -1e30f, mt1 = -1e30f;
        #pragma unroll
        for (int nb = 0; nb < 8; nb++) {
            mt0 = fmaxf(mt0, fmaxf(s[nb][0], s[nb][1]));
            mt1 = fmaxf(mt1, fmaxf(s[nb][2], s[nb][3]));
        }
        #pragma unroll
        for (int off = 1; off < 4; off <<= 1) {
            mt0 = fmaxf(mt0, __shfl_xor_sync(0xffffffffu, mt0, off));
            mt1 = fmaxf(mt1, __shfl_xor_sync(0xffffffffu, mt1, off));
        }
        float mn0 = fmaxf(m0, mt0), mn1 = fmaxf(m1, mt1);
        float f0 = __expf(m0 - mn0), f1 = __expf(m1 - mn1);
        float lt0 = 0.f, lt1 = 0.f;
        #pragma unroll
        for (int nb = 0; nb < 8; nb++) {
            s[nb][0] = __expf(s[nb][0] - mn0); lt0 += s[nb][0];
            s[nb][1] = __expf(s[nb][1] - mn0); lt0 += s[nb][1];
            s[nb][2] = __expf(s[nb][2] - mn1); lt1 += s[nb][2];
            s[nb][3] = __expf(s[nb][3] - mn1); lt1 += s[nb][3];
        }
        #pragma unroll
        for (int off = 1; off < 4; off <<= 1) {
            lt0 += __shfl_xor_sync(0xffffffffu, lt0, off);
            lt1 += __shfl_xor_sync(0xffffffffu, lt1, off);
        }
        l0 = l0 * f0 + lt0;  l1 = l1 * f1 + lt1;
        m0 = mn0;            m1 = mn1;
        #pragma unroll
        for (int nb = 0; nb < 8; nb++) {
            o[nb][0] *= f0; o[nb][1] *= f0;
            o[nb][2] *= f1; o[nb][3] *= f1;
        }

        // ---- P fragments (register repack, fp16) ----
        u32 ap[4][4];
        #pragma unroll
        for (int kp = 0; kp < 4; kp++) {
            ap[kp][0] = packh2(s[2*kp][0],   s[2*kp][1]);
            ap[kp][1] = packh2(s[2*kp][2],   s[2*kp][3]);
            ap[kp][2] = packh2(s[2*kp+1][0], s[2*kp+1][1]);
            ap[kp][3] = packh2(s[2*kp+1][2], s[2*kp+1][3]);
        }

        // ---- O += P V ----
        #pragma unroll
        for (int kp = 0; kp < 4; kp++) {
            #pragma unroll
            for (int dp = 0; dp < 4; dp++) {
                u32 vf[4];
                int row = kp * 16 + (g_ & 1) * 8 + rw;
                ldsm4t(vf, sV + sw128((u32)(row * 128 + dp * 32 + (g_ >> 1) * 16)));
                mma_f16(o[dp * 2],     ap[kp], vf);
                mma_f16(o[dp * 2 + 1], ap[kp], vf + 2);
            }
        }
        __syncthreads();
    }

    float r0 = 1.f / l0, r1 = 1.f / l1;
    #pragma unroll
    for (int nb = 0; nb < 8; nb++) {
        size_t i0 = (size_t)(b * S_ + gq0) * D_ + h * 64 + nb * 8 + (lane & 3) * 2;
        size_t i1 = i0 + 8LL * D_;
        *(ushort2*)(cf + i0) = make_ushort2(f2h(o[nb][0] * r0), f2h(o[nb][1] * r0));
        *(ushort2*)(cf + i1) = make_ushort2(f2h(o[nb][2] * r1), f2h(o[nb][3] * r1));
    }
}

// ---------------- launch ----------------
extern "C" void kernel_launch(void* const* d_in, const int* in_sizes, int n_in,
                              void* d_out, int out_size)
{
    const void*  tok     = d_in[0];
    const float* tok_emb = (const float*)d_in[1];
    const float* gamma1  = (const float*)d_in[2];
    const float* beta1   = (const float*)d_in[3];
    const float* wq      = (const float*)d_in[4];
    const float* bq      = (const float*)d_in[5];
    const float* wk      = (const float*)d_in[6];
    const float* bk      = (const float*)d_in[7];
    const float* wv      = (const float*)d_in[8];
    const float* bv      = (const float*)d_in[9];
    const float* wo      = (const float*)d_in[10];
    const float* bo      = (const float*)d_in[11];
    const float* gamma2  = (const float*)d_in[12];
    const float* beta2   = (const float*)d_in[13];
    const float* w1      = (const float*)d_in[14];
    const float* b1      = (const float*)d_in[15];
    const float* w2      = (const float*)d_in[16];
    const float* b2      = (const float*)d_in[17];
    const float* gamma_f = (const float*)d_in[18];
    const float* beta_f  = (const float*)d_in[19];
    const float* w_out   = (const float*)d_in[20];
    const float* b_out   = (const float*)d_in[21];
    float* out = (float*)d_out;

    float *x;
    u16 *hf, *cf, *f16, *q16b, *k16b, *v16b;
    u16 *q16, *k16, *v16, *o16, *w116, *w216, *wvh, *wvl;
    cudaGetSymbolAddress((void**)&x, g_x);
    cudaGetSymbolAddress((void**)&hf, g_hf);
    cudaGetSymbolAddress((void**)&cf, g_cf);
    cudaGetSymbolAddress((void**)&f16, g_f16);
    cudaGetSymbolAddress((void**)&q16b, g_q16); cudaGetSymbolAddress((void**)&k16b, g_k16);
    cudaGetSymbolAddress((void**)&v16b, g_v16);
    cudaGetSymbolAddress((void**)&q16, t_q16); cudaGetSymbolAddress((void**)&k16, t_k16);
    cudaGetSymbolAddress((void**)&v16, t_v16); cudaGetSymbolAddress((void**)&o16, t_o16);
    cudaGetSymbolAddress((void**)&w116, t_116); cudaGetSymbolAddress((void**)&w216, t_216);
    cudaGetSymbolAddress((void**)&wvh, t_wh); cudaGetSymbolAddress((void**)&wvl, t_wl);

    cudaFuncSetAttribute(attn_kernel, cudaFuncAttributeMaxDynamicSharedMemorySize, ATT_SMEM);
    cudaFuncSetAttribute(hgemm<1,512>,  cudaFuncAttributeMaxDynamicSharedMemorySize, HSMEM);
    cudaFuncSetAttribute(hgemm<2,512>,  cudaFuncAttributeMaxDynamicSharedMemorySize, HSMEM);
    cudaFuncSetAttribute(hgemm<2,2048>, cudaFuncAttributeMaxDynamicSharedMemorySize, HSMEM);
    cudaFuncSetAttribute(hgemm<3,512>,  cudaFuncAttributeMaxDynamicSharedMemorySize, HSMEM);
    cudaFuncSetAttribute(vgemm,         cudaFuncAttributeMaxDynamicSharedMemorySize, VSMEM);

    // weight prep
    dim3 tb(32, 8);
    tcvt_h<<<dim3(16, 16, 4),  tb>>>(wq, q16, D_, D_);
    tcvt_h<<<dim3(16, 16, 4),  tb>>>(wk, k16, D_, D_);
    tcvt_h<<<dim3(16, 16, 4),  tb>>>(wv, v16, D_, D_);
    tcvt_h<<<dim3(16, 16, 4),  tb>>>(wo, o16, D_, D_);
    tcvt_h<<<dim3(64, 16, 4),  tb>>>(w1, w116, D_, F_);
    tcvt_h<<<dim3(16, 64, 4),  tb>>>(w2, w216, F_, D_);
    tcvt_h2<<<dim3(1000, 16), tb>>>(w_out, wvh, wvl, D_, V_);

    embed_kernel<<<M_, 256>>>(tok, tok_emb, x);

    dim3 gD(32, 4);      // N=512
    dim3 gF(32, 16);     // N=2048
    dim3 gV(32, 250);    // N=32000

    for (int l = 0; l < 4; l++) {
        size_t od = (size_t)l * D_ * D_, of = (size_t)l * D_ * F_;
        ln_kernel<<<M_, 128>>>(x, gamma1 + l*D_, beta1 + l*D_, hf);
        hgemm<3,512><<<gD, 256, HSMEM>>>(hf, q16+od, bq + l*D_, 0, q16b, D_);
        hgemm<3,512><<<gD, 256, HSMEM>>>(hf, k16+od, bk + l*D_, 0, k16b, D_);
        hgemm<3,512><<<gD, 256, HSMEM>>>(hf, v16+od, bv + l*D_, 0, v16b, D_);
        attn_kernel<<<dim3(S_/64, B_*H_), 128, ATT_SMEM>>>(q16b, k16b, v16b, cf);
        hgemm<2,512><<<gD, 256, HSMEM>>>(cf, o16+od, bo + l*D_, x, 0, D_);
        ln_kernel<<<M_, 128>>>(x, gamma2 + l*D_, beta2 + l*D_, hf);
        hgemm<1,512><<<gF, 256, HSMEM>>>(hf, w116+of, b1 + l*F_, 0, f16, F_);
        hgemm<2,2048><<<gD, 256, HSMEM>>>(f16, w216+of, b2 + l*D_, x, 0, D_);
    }
    ln_kernel<<<M_, 128>>>(x, gamma_f, beta_f, hf);
    vgemm<<<gV, 256, VSMEM>>>(hf, wvh, wvl, b_out, out, V_);
}

// round 14
// speedup vs baseline: 2.0202x; 1.0013x over previous
#include <cuda_runtime.h>
#include <cuda_fp16.h>
#include <math.h>

#define B_   4
#define S_   1024
#define D_   512
#define H_   8
#define DK_  64
#define F_   2048
#define V_   32000
#define M_   4096

typedef unsigned short u16;
typedef unsigned int   u32;
typedef unsigned long long u64;

// ---------------- scratch (device globals: allocation-free) ----------------
__device__ float g_x [M_*D_];                    // residual stream fp32
__device__ u16   g_hf[M_*D_];                    // LN out, fp16
__device__ u16   g_q16[M_*D_], g_k16[M_*D_], g_v16[M_*D_];  // [B,H,S,DK] fp16
__device__ u16   g_cf[M_*D_];                    // attention ctx, fp16
__device__ u16   g_f16[M_*F_];                   // FFN hidden (GELU out), fp16
// transposed weights [N,K] fp16
__device__ u16 t_q16[4*D_*D_], t_k16[4*D_*D_], t_v16[4*D_*D_], t_o16[4*D_*D_];
__device__ u16 t_116[4*D_*F_], t_216[4*D_*F_];
__device__ u16 t_wh[V_*D_], t_wl[V_*D_];         // w_out^T fp16 hi + 1024-scaled lo

// ---------------- small helpers ----------------
__device__ __forceinline__ u16 f2h(float x){ __half h = __float2half_rn(x); return *(u16*)&h; }
__device__ __forceinline__ void split2h(float a, u16& h, u16& l){
    __half hh = __float2half_rn(a);
    h = *(u16*)&hh;
    l = f2h((a - __half2float(hh)) * 1024.f);
}
__device__ __forceinline__ u32 packh2(float a, float b){
    __half2 h = __floats2half2_rn(a, b);
    return *(u32*)&h;
}
__device__ __forceinline__ u32 s2u(const void* p){
    u32 a; asm("{ .reg .u64 t; cvta.to.shared.u64 t, %1; cvt.u32.u64 %0, t; }" : "=r"(a) : "l"(p));
    return a;
}
__device__ __forceinline__ u32 sw128(u32 x){ return x ^ ((x >> 3) & 0x70); }

__device__ __forceinline__ void ldsm4(u32* r, u32 a){
    asm volatile("ldmatrix.sync.aligned.m8n8.x4.shared.b16 {%0,%1,%2,%3}, [%4];"
        : "=r"(r[0]), "=r"(r[1]), "=r"(r[2]), "=r"(r[3]) : "r"(a));
}
__device__ __forceinline__ void ldsm4t(u32* r, u32 a){
    asm volatile("ldmatrix.sync.aligned.m8n8.x4.trans.shared.b16 {%0,%1,%2,%3}, [%4];"
        : "=r"(r[0]), "=r"(r[1]), "=r"(r[2]), "=r"(r[3]) : "r"(a));
}
__device__ __forceinline__ void mma_f16(float* c, const u32* a, const u32* b){
    asm volatile("mma.sync.aligned.m16n8k16.row.col.f32.f16.f16.f32 "
        "{%0,%1,%2,%3}, {%4,%5,%6,%7}, {%8,%9}, {%0,%1,%2,%3};"
        : "+f"(c[0]), "+f"(c[1]), "+f"(c[2]), "+f"(c[3])
        : "r"(a[0]), "r"(a[1]), "r"(a[2]), "r"(a[3]), "r"(b[0]), "r"(b[1]));
}
#define CPA16(dst, src) asm volatile("cp.async.cg.shared.global [%0], [%1], 16;" :: "r"(dst), "l"(src))
#define CPCOMMIT()      asm volatile("cp.async.commit_group;" ::: "memory")
#define CPWAIT(n)       asm volatile("cp.async.wait_group %0;" :: "n"(n) : "memory")

// ---------------- weight transpose kernels ----------------
__global__ void tcvt_h(const float* __restrict__ W, u16* __restrict__ oh, int K, int N)
{
    __shared__ float t[32][33];
    size_t off = (size_t)blockIdx.z * K * N;
    W += off; oh += off;
    int n0 = blockIdx.x * 32, k0 = blockIdx.y * 32;
    int tx = threadIdx.x, ty = threadIdx.y;
    for (int i = ty; i < 32; i += 8)
        t[i][tx] = W[(size_t)(k0 + i) * N + n0 + tx];
    __syncthreads();
    for (int i = ty; i < 32; i += 8)
        oh[(size_t)(n0 + i) * K + k0 + tx] = f2h(t[tx][i]);
}
__global__ void tcvt_h2(const float* __restrict__ W, u16* __restrict__ oh, u16* __restrict__ ol,
                        int K, int N)
{
    __shared__ float t[32][33];
    int n0 = blockIdx.x * 32, k0 = blockIdx.y * 32;
    int tx = threadIdx.x, ty = threadIdx.y;
    for (int i = ty; i < 32; i += 8)
        t[i][tx] = W[(size_t)(k0 + i) * N + n0 + tx];
    __syncthreads();
    for (int i = ty; i < 32; i += 8) {
        size_t o = (size_t)(n0 + i) * K + k0 + tx;
        u16 h, l; split2h(t[tx][i], h, l);
        oh[o] = h; ol[o] = l;
    }
}

// ---------------- embedding + sinusoidal PE ----------------
__global__ void embed_kernel(const void* __restrict__ tokens,
                             const float* __restrict__ emb,
                             float* __restrict__ x)
{
    const unsigned long long* t64 = (const unsigned long long*)tokens;
    bool is64 = true;
    for (int i = 0; i < 64; i++) if (t64[i] >> 32) { is64 = false; break; }
    int row = blockIdx.x;
    int s   = row & (S_ - 1);
    long long t = is64 ? (long long)t64[row] : (long long)((const int*)tokens)[row];
    const float* e = emb + t * D_;
    float* o = x + row * D_;
    const float c1 = -9.210340371976184f / (float)D_;
    for (int c = threadIdx.x; c < D_; c += blockDim.x) {
        float div = expf((float)(c & ~1) * c1);
        float ang = (float)s * div;
        float pe  = (c & 1) ? cosf(ang) : sinf(ang);
        o[c] = e[c] * 22.62741699796952f + pe;
    }
}

// ---------------- LayerNorm -> fp16 ----------------
__global__ void ln_kernel(const float* __restrict__ x,
                          const float* __restrict__ g,
                          const float* __restrict__ b,
                          u16* __restrict__ hf)
{
    int row = blockIdx.x;
    int t   = threadIdx.x;
    float4 v = ((const float4*)(x + row * D_))[t];
    float s  = v.x + v.y + v.z + v.w;
    float s2 = v.x*v.x + v.y*v.y + v.z*v.z + v.w*v.w;
    #pragma unroll
    for (int o = 16; o; o >>= 1) {
        s  += __shfl_xor_sync(0xffffffffu, s,  o);
        s2 += __shfl_xor_sync(0xffffffffu, s2, o);
    }
    __shared__ float ss[4], ss2[4];
    int w = t >> 5;
    if ((t & 31) == 0) { ss[w] = s; ss2[w] = s2; }
    __syncthreads();
    s  = ss[0] + ss[1] + ss[2] + ss[3];
    s2 = ss2[0] + ss2[1] + ss2[2] + ss2[3];
    float mean = s * (1.f / (float)D_);
    float var  = fmaxf(s2 * (1.f / (float)D_) - mean * mean, 0.f);
    float inv  = 1.f / (sqrtf(var) + 1e-6f);
    float4 gv = ((const float4*)g)[t];
    float4 bv = ((const float4*)b)[t];
    float o0 = gv.x * (v.x - mean) * inv + bv.x;
    float o1 = gv.y * (v.y - mean) * inv + bv.y;
    float o2 = gv.z * (v.z - mean) * inv + bv.z;
    float o3 = gv.w * (v.w - mean) * inv + bv.w;
    *(ushort4*)(hf + row * D_ + t * 4) = make_ushort4(f2h(o0), f2h(o1), f2h(o2), f2h(o3));
}

// ================= 1-pass fp16 GEMM (in-layer) =================
// C[M,N] = A[M,K] @ B^T (B stored [N,K], fp16 both).
// EPI: 1 GELU -> fp16; 2 residual (C += v); 3 QKV scatter fp16 [B,H,S,DK].
#define HSMEM (2*32768)

template<int EPI, int K>
__global__ __launch_bounds__(256, 2)
void hgemm(const u16* __restrict__ A, const u16* __restrict__ B,
           const float* __restrict__ bias, float* __restrict__ C,
           u16* __restrict__ Oh, int N)
{
    extern __shared__ __align__(1024) unsigned char smem[];
    const u32 sbase = s2u(smem);
    const int tid = threadIdx.x, wid = tid >> 5, lane = tid & 31;
    const int m0 = blockIdx.x * 128, n0 = blockIdx.y * 128;
    constexpr int NC = K / 64;
    const int wm = (wid >> 1) * 32;
    const int wn = (wid & 1) * 64;

    const u16* srcs[2] = { A + (size_t)m0 * K, B + (size_t)n0 * K };

    float acc[2][8][4];
    #pragma unroll
    for (int i = 0; i < 2; i++)
        #pragma unroll
        for (int j = 0; j < 8; j++)
            #pragma unroll
            for (int q = 0; q < 4; q++) acc[i][j][q] = 0.f;

    auto prefetch = [&](int c, int buf) {
        int k0 = c * 64;
        #pragma unroll
        for (int t = 0; t < 2; t++) {
            const u16* s = srcs[t] + k0;
            u32 dst = sbase + buf * 32768 + t * 16384;
            #pragma unroll
            for (int i = 0; i < 4; i++) {
                int seg = i * 256 + tid;
                int r = seg >> 3, j = seg & 7;
                CPA16(dst + sw128(r * 128 + j * 16), s + (size_t)r * K + j * 8);
            }
        }
        CPCOMMIT();
    };

    const int grp = lane >> 3, rin = lane & 7;

    auto compute = [&](int buf) {
        u32 aB = sbase + buf * 32768, bB = aB + 16384;
        #pragma unroll
        for (int ks = 0; ks < 4; ks++) {
            u32 ah[2][4], bh[4][4];
            #pragma unroll
            for (int mb = 0; mb < 2; mb++) {
                int row = wm + mb * 16 + (grp & 1) * 8 + rin;
                ldsm4(ah[mb], aB + sw128((u32)(row * 128 + ks * 32 + (grp >> 1) * 16)));
            }
            #pragma unroll
            for (int j = 0; j < 4; j++) {
                int row = wn + j * 16 + (grp >> 1) * 8 + rin;
                ldsm4(bh[j], bB + sw128((u32)(row * 128 + ks * 32 + (grp & 1) * 16)));
            }
            #pragma unroll
            for (int mb = 0; mb < 2; mb++)
                #pragma unroll
                for (int j = 0; j < 4; j++)
                    #pragma unroll
                    for (int hf = 0; hf < 2; hf++)
                        mma_f16(acc[mb][j * 2 + hf], ah[mb], bh[j] + hf * 2);
        }
    };

    prefetch(0, 0);
    for (int c = 0; c < NC; c++) {
        int b = c & 1;
        if (c + 1 < NC) {
            prefetch(c + 1, 1 - b);
            CPWAIT(1);
        } else {
            CPWAIT(0);
        }
        __syncthreads();
        compute(b);
        __syncthreads();
    }

    const int rbase = lane >> 2;
    const int cbase = (lane & 3) * 2;
    #pragma unroll
    for (int mb = 0; mb < 2; mb++) {
        #pragma unroll
        for (int nb = 0; nb < 8; nb++) {
            const float* a4 = acc[mb][nb];
            int gr = m0 + wm + mb * 16 + rbase;
            int gc = n0 + wn + nb * 8 + cbase;
            float b0 = __ldg(bias + gc), b1 = __ldg(bias + gc + 1);
            float v00 = a4[0] + b0, v01 = a4[1] + b1;
            float v10 = a4[2] + b0, v11 = a4[3] + b1;
            if (EPI == 2) {
                float2 c0 = *(float2*)(C + (size_t)gr * N + gc);
                float2 c1 = *(float2*)(C + (size_t)(gr + 8) * N + gc);
                c0.x += v00; c0.y += v01; c1.x += v10; c1.y += v11;
                *(float2*)(C + (size_t)gr * N + gc)       = c0;
                *(float2*)(C + (size_t)(gr + 8) * N + gc) = c1;
            } else if (EPI == 3) {
                int h = gc >> 6, dk = gc & 63;
                size_t i0 = ((size_t)((gr >> 10) * H_ + h) * S_ + (gr & (S_ - 1))) * DK_ + dk;
                int gr8 = gr + 8;
                size_t i1 = ((size_t)((gr8 >> 10) * H_ + h) * S_ + (gr8 & (S_ - 1))) * DK_ + dk;
                *(ushort2*)(Oh + i0) = make_ushort2(f2h(v00), f2h(v01));
                *(ushort2*)(Oh + i1) = make_ushort2(f2h(v10), f2h(v11));
            } else { // EPI == 1: exact GELU -> fp16
                float g00 = 0.5f * v00 * (1.f + erff(v00 * 0.70710678118654752f));
                float g01 = 0.5f * v01 * (1.f + erff(v01 * 0.70710678118654752f));
                float g10 = 0.5f * v10 * (1.f + erff(v10 * 0.70710678118654752f));
                float g11 = 0.5f * v11 * (1.f + erff(v11 * 0.70710678118654752f));
                *(ushort2*)(Oh + (size_t)gr * N + gc)       = make_ushort2(f2h(g00), f2h(g01));
                *(ushort2*)(Oh + (size_t)(gr + 8) * N + gc) = make_ushort2(f2h(g10), f2h(g11));
            }
        }
    }
}

// ================= 2-pass fp16 GEMM (logits): A·Bh + A·Bl/1024 =================
#define VSMEM (2*49152)

__global__ __launch_bounds__(256, 1)
void vgemm(const u16* __restrict__ A, const u16* __restrict__ Bh, const u16* __restrict__ Bl,
           const float* __restrict__ bias, float* __restrict__ C, int N)
{
    extern __shared__ __align__(1024) unsigned char smem[];
    const u32 sbase = s2u(smem);
    const int tid = threadIdx.x, wid = tid >> 5, lane = tid & 31;
    const int m0 = blockIdx.x * 128, n0 = blockIdx.y * 128;
    constexpr int K = 512, NC = K / 64;
    const int wm = (wid >> 1) * 32;
    const int wn = (wid & 1) * 64;

    const u16* srcs[3] = { A + (size_t)m0 * K, Bh + (size_t)n0 * K, Bl + (size_t)n0 * K };

    float acch[2][8][4], accl[2][8][4];
    #pragma unroll
    for (int i = 0; i < 2; i++)
        #pragma unroll
        for (int j = 0; j < 8; j++)
            #pragma unroll
            for (int q = 0; q < 4; q++) { acch[i][j][q] = 0.f; accl[i][j][q] = 0.f; }

    auto prefetch = [&](int c, int buf) {
        int k0 = c * 64;
        #pragma unroll
        for (int t = 0; t < 3; t++) {
            const u16* s = srcs[t] + k0;
            u32 dst = sbase + buf * 49152 + t * 16384;
            #pragma unroll
            for (int i = 0; i < 4; i++) {
                int seg = i * 256 + tid;
                int r = seg >> 3, j = seg & 7;
                CPA16(dst + sw128(r * 128 + j * 16), s + (size_t)r * K + j * 8);
            }
        }
        CPCOMMIT();
    };

    const int grp = lane >> 3, rin = lane & 7;

    auto compute = [&](int buf) {
        u32 aB = sbase + buf * 49152, hB = aB + 16384, lB = aB + 32768;
        #pragma unroll
        for (int ks = 0; ks < 4; ks++) {
            u32 ah[2][4], bh[4][4], bl[4][4];
            #pragma unroll
            for (int mb = 0; mb < 2; mb++) {
                int row = wm + mb * 16 + (grp & 1) * 8 + rin;
                ldsm4(ah[mb], aB + sw128((u32)(row * 128 + ks * 32 + (grp >> 1) * 16)));
            }
            #pragma unroll
            for (int j = 0; j < 4; j++) {
                int row = wn + j * 16 + (grp >> 1) * 8 + rin;
                u32 off = sw128((u32)(row * 128 + ks * 32 + (grp & 1) * 16));
                ldsm4(bh[j], hB + off);
                ldsm4(bl[j], lB + off);
            }
            #pragma unroll
            for (int mb = 0; mb < 2; mb++)
                #pragma unroll
                for (int j = 0; j < 4; j++)
                    #pragma unroll
                    for (int hf = 0; hf < 2; hf++) {
                        mma_f16(acch[mb][j * 2 + hf], ah[mb], bh[j] + hf * 2);
                        mma_f16(accl[mb][j * 2 + hf], ah[mb], bl[j] + hf * 2);
                    }
        }
    };

    prefetch(0, 0);
    for (int c = 0; c < NC; c++) {
        int b = c & 1;
        if (c + 1 < NC) {
            prefetch(c + 1, 1 - b);
            CPWAIT(1);
        } else {
            CPWAIT(0);
        }
        __syncthreads();
        compute(b);
        __syncthreads();
    }

    const int rbase = lane >> 2;
    const int cbase = (lane & 3) * 2;
    const float is = 1.f / 1024.f;
    #pragma unroll
    for (int mb = 0; mb < 2; mb++) {
        #pragma unroll
        for (int nb = 0; nb < 8; nb++) {
            int gr = m0 + wm + mb * 16 + rbase;
            int gc = n0 + wn + nb * 8 + cbase;
            float b0 = __ldg(bias + gc), b1 = __ldg(bias + gc + 1);
            float v00 = acch[mb][nb][0] + accl[mb][nb][0] * is + b0;
            float v01 = acch[mb][nb][1] + accl[mb][nb][1] * is + b1;
            float v10 = acch[mb][nb][2] + accl[mb][nb][2] * is + b0;
            float v11 = acch[mb][nb][3] + accl[mb][nb][3] * is + b1;
            *(float2*)(C + (size_t)gr * N + gc)       = make_float2(v00, v01);
            *(float2*)(C + (size_t)(gr + 8) * N + gc) = make_float2(v10, v11);
        }
    }
}

// ================= tensor-core flash attention =================
// 4 warps, 64-query tile per CTA, 64-key tiles, fp16 QK/PV mma, fp32 softmax.
#define ATT_SMEM (8192 + 2*16384)

__global__ __launch_bounds__(128)
void attn_kernel(const u16* __restrict__ q, const u16* __restrict__ k,
                 const u16* __restrict__ v, u16* __restrict__ cf)
{
    extern __shared__ __align__(1024) unsigned char smraw[];
    const u32 sQ = s2u(smraw);
    int qb = blockIdx.x, bh = blockIdx.y;
    int b = bh >> 3, h = bh & 7;
    const u16* qg = q + (size_t)bh * S_ * DK_;
    const u16* kg = k + (size_t)bh * S_ * DK_;
    const u16* vg = v + (size_t)bh * S_ * DK_;
    const int tid = threadIdx.x, wid = tid >> 5, lane = tid & 31;
    const int g_ = lane >> 3, rw = lane & 7;

    // Q tile: 64 rows x 128B, swizzled
    #pragma unroll
    for (int i = 0; i < 4; i++) {
        int seg = i * 128 + tid;
        int r = seg >> 3, j = seg & 7;
        CPA16(sQ + sw128(r * 128 + j * 16), qg + (size_t)(qb * 64 + r) * DK_ + j * 8);
    }
    CPCOMMIT();

    auto ldkv = [&](int kt, int buf) {
        u32 base = sQ + 8192 + buf * 16384;
        #pragma unroll
        for (int i = 0; i < 4; i++) {
            int seg = i * 128 + tid;
            int r = seg >> 3, j = seg & 7;
            u32 off = sw128(r * 128 + j * 16);
            CPA16(base + off,        kg + (size_t)(kt * 64 + r) * DK_ + j * 8);
            CPA16(base + 8192 + off, vg + (size_t)(kt * 64 + r) * DK_ + j * 8);
        }
        CPCOMMIT();
    };
    ldkv(0, 0);

    CPWAIT(1);            // Q done
    __syncthreads();
    u32 qf[4][4];
    #pragma unroll
    for (int ks = 0; ks < 4; ks++) {
        int row = wid * 16 + (g_ & 1) * 8 + rw;
        ldsm4(qf[ks], sQ + sw128((u32)(row * 128 + ks * 32 + (g_ >> 1) * 16)));
    }

    float m0 = -1e30f, m1 = -1e30f, l0 = 0.f, l1 = 0.f;
    float o[8][4];
    #pragma unroll
    for (int nb = 0; nb < 8; nb++)
        #pragma unroll
        for (int qq = 0; qq < 4; qq++) o[nb][qq] = 0.f;
    const int gq0 = qb * 64 + wid * 16 + (lane >> 2);   // row for c0,c1; c2,c3 at +8

    for (int kt = 0; kt <= qb; kt++) {
        int buf = kt & 1;
        if (kt < qb) { ldkv(kt + 1, 1 - buf); CPWAIT(1); }
        else         { CPWAIT(0); }
        __syncthreads();
        u32 sK = sQ + 8192 + buf * 16384, sV = sK + 8192;

        // ---- S = Q K^T ----
        float s[8][4];
        #pragma unroll
        for (int nb = 0; nb < 8; nb++)
            #pragma unroll
            for (int qq = 0; qq < 4; qq++) s[nb][qq] = 0.f;
        #pragma unroll
        for (int ks = 0; ks < 4; ks++) {
            #pragma unroll
            for (int kp = 0; kp < 4; kp++) {
                u32 kf[4];
                int row = kp * 16 + (g_ >> 1) * 8 + rw;
                ldsm4(kf, sK + sw128((u32)(row * 128 + ks * 32 + (g_ & 1) * 16)));
                mma_f16(s[kp * 2],     qf[ks], kf);
                mma_f16(s[kp * 2 + 1], qf[ks], kf + 2);
            }
        }

        // ---- scale + causal mask (diagonal tile only) ----
        if (kt == qb) {
            #pragma unroll
            for (int nb = 0; nb < 8; nb++) {
                int gk = kt * 64 + nb * 8 + (lane & 3) * 2;
                s[nb][0] = (gk     <= gq0)     ? s[nb][0] * 0.125f : -1e9f;
                s[nb][1] = (gk + 1 <= gq0)     ? s[nb][1] * 0.125f : -1e9f;
                s[nb][2] = (gk     <= gq0 + 8) ? s[nb][2] * 0.125f : -1e9f;
                s[nb][3] = (gk + 1 <= gq0 + 8) ? s[nb][3] * 0.125f : -1e9f;
            }
        } else {
            #pragma unroll
            for (int nb = 0; nb < 8; nb++)
                #pragma unroll
                for (int qq = 0; qq < 4; qq++) s[nb][qq] *= 0.125f;
        }

        // ---- online softmax ----
        float mt0 = -1e30f, mt1 = -1e30f;
        #pragma unroll
        for (int nb = 0; nb < 8; nb++) {
            mt0 = fmaxf(mt0, fmaxf(s[nb][0], s[nb][1]));
            mt1 = fmaxf(mt1, fmaxf(s[nb][2], s[nb][3]));
        }
        #pragma unroll
        for (int off = 1; off < 4; off <<= 1) {
            mt0 = fmaxf(mt0, __shfl_xor_sync(0xffffffffu, mt0, off));
            mt1 = fmaxf(mt1, __shfl_xor_sync(0xffffffffu, mt1, off));
        }
        float mn0 = fmaxf(m0, mt0), mn1 = fmaxf(m1, mt1);
        float f0 = __expf(m0 - mn0), f1 = __expf(m1 - mn1);
        float lt0 = 0.f, lt1 = 0.f;
        #pragma unroll
        for (int nb = 0; nb < 8; nb++) {
            s[nb][0] = __expf(s[nb][0] - mn0); lt0 += s[nb][0];
            s[nb][1] = __expf(s[nb][1] - mn0); lt0 += s[nb][1];
            s[nb][2] = __expf(s[nb][2] - mn1); lt1 += s[nb][2];
            s[nb][3] = __expf(s[nb][3] - mn1); lt1 += s[nb][3];
        }
        #pragma unroll
        for (int off = 1; off < 4; off <<= 1) {
            lt0 += __shfl_xor_sync(0xffffffffu, lt0, off);
            lt1 += __shfl_xor_sync(0xffffffffu, lt1, off);
        }
        l0 = l0 * f0 + lt0;  l1 = l1 * f1 + lt1;
        m0 = mn0;            m1 = mn1;
        #pragma unroll
        for (int nb = 0; nb < 8; nb++) {
            o[nb][0] *= f0; o[nb][1] *= f0;
            o[nb][2] *= f1; o[nb][3] *= f1;
        }

        // ---- P fragments (register repack, fp16) ----
        u32 ap[4][4];
        #pragma unroll
        for (int kp = 0; kp < 4; kp++) {
            ap[kp][0] = packh2(s[2*kp][0],   s[2*kp][1]);
            ap[kp][1] = packh2(s[2*kp][2],   s[2*kp][3]);
            ap[kp][2] = packh2(s[2*kp+1][0], s[2*kp+1][1]);
            ap[kp][3] = packh2(s[2*kp+1][2], s[2*kp+1][3]);
        }

        // ---- O += P V ----
        #pragma unroll
        for (int kp = 0; kp < 4; kp++) {
            #pragma unroll
            for (int dp = 0; dp < 4; dp++) {
                u32 vf[4];
                int row = kp * 16 + (g_ & 1) * 8 + rw;
                ldsm4t(vf, sV + sw128((u32)(row * 128 + dp * 32 + (g_ >> 1) * 16)));
                mma_f16(o[dp * 2],     ap[kp], vf);
                mma_f16(o[dp * 2 + 1], ap[kp], vf + 2);
            }
        }
        __syncthreads();
    }

    float r0 = 1.f / l0, r1 = 1.f / l1;
    #pragma unroll
    for (int nb = 0; nb < 8; nb++) {
        size_t i0 = (size_t)(b * S_ + gq0) * D_ + h * 64 + nb * 8 + (lane & 3) * 2;
        size_t i1 = i0 + 8LL * D_;
        *(ushort2*)(cf + i0) = make_ushort2(f2h(o[nb][0] * r0), f2h(o[nb][1] * r0));
        *(ushort2*)(cf + i1) = make_ushort2(f2h(o[nb][2] * r1), f2h(o[nb][3] * r1));
    }
}

// ---------------- launch ----------------
extern "C" void kernel_launch(void* const* d_in, const int* in_sizes, int n_in,
                              void* d_out, int out_size)
{
    const void*  tok     = d_in[0];
    const float* tok_emb = (const float*)d_in[1];
    const float* gamma1  = (const float*)d_in[2];
    const float* beta1   = (const float*)d_in[3];
    const float* wq      = (const float*)d_in[4];
    const float* bq      = (const float*)d_in[5];
    const float* wk      = (const float*)d_in[6];
    const float* bk      = (const float*)d_in[7];
    const float* wv      = (const float*)d_in[8];
    const float* bv      = (const float*)d_in[9];
    const float* wo      = (const float*)d_in[10];
    const float* bo      = (const float*)d_in[11];
    const float* gamma2  = (const float*)d_in[12];
    const float* beta2   = (const float*)d_in[13];
    const float* w1      = (const float*)d_in[14];
    const float* b1      = (const float*)d_in[15];
    const float* w2      = (const float*)d_in[16];
    const float* b2      = (const float*)d_in[17];
    const float* gamma_f = (const float*)d_in[18];
    const float* beta_f  = (const float*)d_in[19];
    const float* w_out   = (const float*)d_in[20];
    const float* b_out   = (const float*)d_in[21];
    float* out = (float*)d_out;

    float *x;
    u16 *hf, *cf, *f16, *q16b, *k16b, *v16b;
    u16 *q16, *k16, *v16, *o16, *w116, *w216, *wvh, *wvl;
    cudaGetSymbolAddress((void**)&x, g_x);
    cudaGetSymbolAddress((void**)&hf, g_hf);
    cudaGetSymbolAddress((void**)&cf, g_cf);
    cudaGetSymbolAddress((void**)&f16, g_f16);
    cudaGetSymbolAddress((void**)&q16b, g_q16); cudaGetSymbolAddress((void**)&k16b, g_k16);
    cudaGetSymbolAddress((void**)&v16b, g_v16);
    cudaGetSymbolAddress((void**)&q16, t_q16); cudaGetSymbolAddress((void**)&k16, t_k16);
    cudaGetSymbolAddress((void**)&v16, t_v16); cudaGetSymbolAddress((void**)&o16, t_o16);
    cudaGetSymbolAddress((void**)&w116, t_116); cudaGetSymbolAddress((void**)&w216, t_216);
    cudaGetSymbolAddress((void**)&wvh, t_wh); cudaGetSymbolAddress((void**)&wvl, t_wl);

    cudaFuncSetAttribute(attn_kernel, cudaFuncAttributeMaxDynamicSharedMemorySize, ATT_SMEM);
    cudaFuncSetAttribute(hgemm<1,512>,  cudaFuncAttributeMaxDynamicSharedMemorySize, HSMEM);
    cudaFuncSetAttribute(hgemm<2,512>,  cudaFuncAttributeMaxDynamicSharedMemorySize, HSMEM);
    cudaFuncSetAttribute(hgemm<2,2048>, cudaFuncAttributeMaxDynamicSharedMemorySize, HSMEM);
    cudaFuncSetAttribute(hgemm<3,512>,  cudaFuncAttributeMaxDynamicSharedMemorySize, HSMEM);
    cudaFuncSetAttribute(vgemm,         cudaFuncAttributeMaxDynamicSharedMemorySize, VSMEM);

    // weight prep
    dim3 tb(32, 8);
    tcvt_h<<<dim3(16, 16, 4),  tb>>>(wq, q16, D_, D_);
    tcvt_h<<<dim3(16, 16, 4),  tb>>>(wk, k16, D_, D_);
    tcvt_h<<<dim3(16, 16, 4),  tb>>>(wv, v16, D_, D_);
    tcvt_h<<<dim3(16, 16, 4),  tb>>>(wo, o16, D_, D_);
    tcvt_h<<<dim3(64, 16, 4),  tb>>>(w1, w116, D_, F_);
    tcvt_h<<<dim3(16, 64, 4),  tb>>>(w2, w216, F_, D_);
    tcvt_h2<<<dim3(1000, 16), tb>>>(w_out, wvh, wvl, D_, V_);

    embed_kernel<<<M_, 256>>>(tok, tok_emb, x);

    dim3 gD(32, 4);      // N=512
    dim3 gF(32, 16);     // N=2048
    dim3 gV(32, 250);    // N=32000

    for (int l = 0; l < 4; l++) {
        size_t od = (size_t)l * D_ * D_, of = (size_t)l * D_ * F_;
        ln_kernel<<<M_, 128>>>(x, gamma1 + l*D_, beta1 + l*D_, hf);
        hgemm<3,512><<<gD, 256, HSMEM>>>(hf, q16+od, bq + l*D_, 0, q16b, D_);
        hgemm<3,512><<<gD, 256, HSMEM>>>(hf, k16+od, bk + l*D_, 0, k16b, D_);
        hgemm<3,512><<<gD, 256, HSMEM>>>(hf, v16+od, bv + l*D_, 0, v16b, D_);
        attn_kernel<<<dim3(S_/64, B_*H_), 128, ATT_SMEM>>>(q16b, k16b, v16b, cf);
        hgemm<2,512><<<gD, 256, HSMEM>>>(cf, o16+od, bo + l*D_, x, 0, D_);
        ln_kernel<<<M_, 128>>>(x, gamma2 + l*D_, beta2 + l*D_, hf);
        hgemm<1,512><<<gF, 256, HSMEM>>>(hf, w116+of, b1 + l*F_, 0, f16, F_);
        hgemm<2,2048><<<gD, 256, HSMEM>>>(f16, w216+of, b2 + l*D_, x, 0, D_);
    }
    ln_kernel<<<M_, 128>>>(x, gamma_f, beta_f, hf);
    vgemm<<<gV, 256, VSMEM>>>(hf, wvh, wvl, b_out, out, V_);
}